// round 16
// baseline (speedup 1.0000x reference)
#include <cuda_runtime.h>
#include <cuda_fp16.h>
#include <cstdint>

#define EMBED 2048
#define HD    128
#define NB    4
#define SEQ   2048

// ---------------------------------------------------------------------------
// Scratch globals
// ---------------------------------------------------------------------------
__device__ __align__(16) __half g_Wh[3 * HD * EMBED];       // rne fp16 [w][n][k]
__device__ __align__(16) __half g_xh[(size_t)NB * SEQ * EMBED]; // rne fp16
__device__ __align__(16) __half g_q [NB * SEQ * HD];        // [b][s][d]
__device__ __align__(16) __half g_k [NB * SEQ * HD];        // [b][s][d]
__device__ __align__(16) __half g_vt[NB * HD * SEQ];        // [b][d][s]

__device__ __forceinline__ uint32_t pk2h(__half a, __half b) {
    return ((uint32_t)__half_as_ushort(b) << 16) | __half_as_ushort(a);
}
__device__ __forceinline__ uint32_t smem_u32(const void* p) {
    uint32_t a;
    asm("{ .reg .u64 t; cvta.to.shared.u64 t, %1; cvt.u32.u64 %0, t; }"
        : "=r"(a) : "l"(p));
    return a;
}
__device__ __forceinline__ void mma16816h(float* c, const uint32_t* a,
                                          const uint32_t* b) {
    asm volatile(
        "mma.sync.aligned.m16n8k16.row.col.f32.f16.f16.f32 "
        "{%0,%1,%2,%3}, {%4,%5,%6,%7}, {%8,%9}, {%0,%1,%2,%3};"
        : "+f"(c[0]), "+f"(c[1]), "+f"(c[2]), "+f"(c[3])
        : "r"(a[0]), "r"(a[1]), "r"(a[2]), "r"(a[3]), "r"(b[0]), "r"(b[1]));
}
__device__ __forceinline__ void ldsm4(uint32_t* r, uint32_t saddr) {
    asm volatile("ldmatrix.sync.aligned.m8n8.x4.shared.b16 {%0,%1,%2,%3}, [%4];"
                 : "=r"(r[0]), "=r"(r[1]), "=r"(r[2]), "=r"(r[3]) : "r"(saddr));
}
__device__ __forceinline__ void ldsm2(uint32_t* r, uint32_t saddr) {
    asm volatile("ldmatrix.sync.aligned.m8n8.x2.shared.b16 {%0,%1}, [%2];"
                 : "=r"(r[0]), "=r"(r[1]) : "r"(saddr));
}
__device__ __forceinline__ void cpa16(uint32_t dst, const void* src) {
    asm volatile("cp.async.cg.shared.global [%0], [%1], 16;"
                 :: "r"(dst), "l"(__cvta_generic_to_global(src)) : "memory");
}
#define CP_COMMIT() asm volatile("cp.async.commit_group;" ::: "memory")
#define CP_WAIT1()  asm volatile("cp.async.wait_group 1;" ::: "memory")

// ---------------------------------------------------------------------------
// prep_w (unchanged): W fp32 [k][n] -> rne fp16 [w][n][k]. grid = 192.
// ---------------------------------------------------------------------------
__global__ __launch_bounds__(256)
void prep_w(const float* __restrict__ Wq, const float* __restrict__ Wk,
            const float* __restrict__ Wv)
{
    __shared__ float Ws[32][132];
    const int t = threadIdx.x;
    const int w  = blockIdx.x >> 6;
    const int k0 = (blockIdx.x & 63) * 32;
    const float* __restrict__ W = (w == 0) ? Wq : (w == 1 ? Wk : Wv);

    #pragma unroll
    for (int l = 0; l < 16; ++l) {
        int idx = t + l * 256;
        int kk = idx >> 7, n = idx & 127;
        Ws[kk][n] = W[(size_t)(k0 + kk) * HD + n];
    }
    __syncthreads();

    const int n = t >> 1, kh = (t & 1) * 16;
    __half* dst = g_Wh + (size_t)w * HD * EMBED + (size_t)n * EMBED + k0 + kh;
    #pragma unroll
    for (int g = 0; g < 2; ++g) {
        uint32_t hp[4];
        #pragma unroll
        for (int e = 0; e < 4; ++e)
            hp[e] = pk2h(__float2half(Ws[kh + g * 8 + e * 2][n]),
                         __float2half(Ws[kh + g * 8 + e * 2 + 1][n]));
        *(uint4*)(dst + g * 8) = make_uint4(hp[0], hp[1], hp[2], hp[3]);
    }
}

// ---------------------------------------------------------------------------
// prep_x (unchanged): X fp32 -> rne fp16. grid = 512.
// ---------------------------------------------------------------------------
__global__ __launch_bounds__(256)
void prep_x(const float* __restrict__ X)
{
    const size_t N8 = (size_t)NB * SEQ * EMBED / 8;
    const size_t nthr = 512 * 256;
    for (size_t c = (size_t)blockIdx.x * 256 + threadIdx.x; c < N8; c += nthr) {
        float4 v0 = *(const float4*)(X + c * 8);
        float4 v1 = *(const float4*)(X + c * 8 + 4);
        uint4 o;
        o.x = pk2h(__float2half(v0.x), __float2half(v0.y));
        o.y = pk2h(__float2half(v0.z), __float2half(v0.w));
        o.z = pk2h(__float2half(v1.x), __float2half(v1.y));
        o.w = pk2h(__float2half(v1.z), __float2half(v1.w));
        *(uint4*)(g_xh + c * 8) = o;
    }
}

// ---------------------------------------------------------------------------
// qkv6 (R14-passing, reverted): FP16 GEMM, KC=32, grid (128, 3), 3 CTAs/SM.
// ---------------------------------------------------------------------------
#define KC    32
#define LDB   40
#define A6STG (64 * LDB * 2)
#define B6STG (128 * LDB * 2)
#define O6_A  0
#define O6_B  (2 * A6STG)
#define O6_BIAS 34048
#define QSM6_TOTAL (O6_BIAS + 512)

__global__ __launch_bounds__(256, 3)
void qkv6(const float* __restrict__ bq, const float* __restrict__ bk,
          const float* __restrict__ bv)
{
    extern __shared__ char smem[];
    const uint32_t sb = smem_u32(smem);
    float* biasS = (float*)(smem + O6_BIAS);

    const int wsel = blockIdx.y;
    const int m0   = blockIdx.x * 64;
    const int t    = threadIdx.x;
    const int wid  = t >> 5, lane = t & 31;
    const int g    = lane >> 2, tig = lane & 3;
    const int wm   = wid >> 2, wn = wid & 3;

    const int aiA = (((lane >> 3) & 1) * 8 + (lane & 7)) * LDB + (lane >> 4) * 8;
    const int biB = ((lane >> 4) * 8 + (lane & 7)) * LDB + ((lane >> 3) & 1) * 8;

    if (t < 128) {
        const float* bias = (wsel == 0) ? bq : (wsel == 1 ? bk : bv);
        biasS[t] = bias[t];
    }

    const __half* Wh = g_Wh + (size_t)wsel * HD * EMBED;
    const int ar = t >> 2, aq = t & 3;
    const int br = t >> 1, bhh = t & 1;

    float c[2][4][4];
    #pragma unroll
    for (int i = 0; i < 2; ++i)
        #pragma unroll
        for (int j = 0; j < 4; ++j)
            #pragma unroll
            for (int q = 0; q < 4; ++q) c[i][j][q] = 0.f;

    #pragma unroll
    for (int pi = 0; pi < 2; ++pi) {
        const int kb = pi * KC;
        cpa16(sb + O6_A + pi * A6STG + ar * (LDB * 2) + aq * 16,
              g_xh + (size_t)(m0 + ar) * EMBED + kb + aq * 8);
        {
            const __half* src = Wh + (size_t)br * EMBED + kb + bhh * 16;
            const uint32_t dst = sb + O6_B + pi * B6STG + br * (LDB * 2) + bhh * 32;
            cpa16(dst, src);
            cpa16(dst + 16, src + 8);
        }
        CP_COMMIT();
    }

    for (int kt = 0; kt < EMBED / KC; ++kt) {
        const int st = kt & 1;
        const uint32_t sA = sb + O6_A + st * A6STG;
        const uint32_t sB = sb + O6_B + st * B6STG;

        CP_WAIT1();
        __syncthreads();

        #pragma unroll
        for (int ks = 0; ks < 2; ++ks) {
            const int ko = ks * 16;
            uint32_t a[2][4], bb[2][4];
            #pragma unroll
            for (int mi = 0; mi < 2; ++mi)
                ldsm4(a[mi], sA + 2 * ((wm * 32 + mi * 16) * LDB + ko + aiA));
            #pragma unroll
            for (int h = 0; h < 2; ++h)
                ldsm4(bb[h], sB + 2 * ((wn * 32 + h * 16) * LDB + ko + biB));
            #pragma unroll
            for (int mi = 0; mi < 2; ++mi)
                #pragma unroll
                for (int nt = 0; nt < 4; ++nt)
                    mma16816h(c[mi][nt], a[mi], &bb[nt >> 1][(nt & 1) * 2]);
        }
        __syncthreads();

        if (kt + 2 < EMBED / KC) {
            const int kb = (kt + 2) * KC;
            cpa16(sb + O6_A + st * A6STG + ar * (LDB * 2) + aq * 16,
                  g_xh + (size_t)(m0 + ar) * EMBED + kb + aq * 8);
            {
                const __half* src = Wh + (size_t)br * EMBED + kb + bhh * 16;
                const uint32_t dst = sb + O6_B + st * B6STG + br * (LDB * 2) + bhh * 32;
                cpa16(dst, src);
                cpa16(dst + 16, src + 8);
            }
        }
        CP_COMMIT();
    }

    __syncthreads();
    float (*Ct)[132] = (float (*)[132])smem;
    #pragma unroll
    for (int mi = 0; mi < 2; ++mi) {
        const int r = wm * 32 + mi * 16 + g;
        #pragma unroll
        for (int nt = 0; nt < 4; ++nt) {
            const int n = wn * 32 + nt * 8 + tig * 2;
            Ct[r][n]         = c[mi][nt][0] + biasS[n];
            Ct[r][n + 1]     = c[mi][nt][1] + biasS[n + 1];
            Ct[r + 8][n]     = c[mi][nt][2] + biasS[n];
            Ct[r + 8][n + 1] = c[mi][nt][3] + biasS[n + 1];
        }
    }
    __syncthreads();

    const int batch = m0 >> 11, s0 = m0 & 2047;
    if (wsel < 2) {
        const int r = t >> 2, dq = (t & 3) * 32;
        __half* dst = (wsel == 0 ? g_q : g_k)
            + ((size_t)batch * SEQ + s0 + r) * HD + dq;
        #pragma unroll
        for (int qq = 0; qq < 4; ++qq) {
            uint32_t hp[4];
            #pragma unroll
            for (int e = 0; e < 4; ++e)
                hp[e] = pk2h(__float2half(Ct[r][dq + qq * 8 + e * 2]),
                             __float2half(Ct[r][dq + qq * 8 + e * 2 + 1]));
            *(uint4*)(dst + qq * 8) = make_uint4(hp[0], hp[1], hp[2], hp[3]);
        }
    } else {
        const int d = t >> 1, sch = (t & 1) * 32;
        __half* dst = g_vt + ((size_t)batch * HD + d) * SEQ + s0 + sch;
        #pragma unroll
        for (int qq = 0; qq < 4; ++qq) {
            uint32_t hp[4];
            #pragma unroll
            for (int e = 0; e < 4; ++e)
                hp[e] = pk2h(__float2half(Ct[sch + qq * 8 + e * 2][d]),
                             __float2half(Ct[sch + qq * 8 + e * 2 + 1][d]));
            *(uint4*)(dst + qq * 8) = make_uint4(hp[0], hp[1], hp[2], hp[3]);
        }
    }
}

// ---------------------------------------------------------------------------
// attn9: 16-row q-tiles, grid (64, 4) = 256 CTAs -> 2 CTAs/SM co-residency.
// Pairing {x, 127-x}: every CTA exactly 33 k-iters. KT=64, fp16 single,
// cp.async 2-stage. smem 83 KB.
// ---------------------------------------------------------------------------
#define KT   64
#define LDK  136
#define LDV  72
#define LDP  72
#define SPS  68
#define KSTG (KT * LDK * 2)      // 17408
#define VSTG (HD * LDV * 2)      // 18432

#define A9_Q    0                            // 16*136*2 = 4352
#define A9_K    4352                         // 2*17408 -> 39168
#define A9_V    39168                        // 2*18432 -> 76032
#define A9_PS   76032                        // 16*68*4 = 4352 -> 80384
#define A9_PB   80384                        // 16*72*2 = 2304 -> 82688
#define A9_MLA  82688                        // 3*16*4 = 192
#define ASM9_TOTAL 82880

__global__ __launch_bounds__(256, 2)
void attn9(float* __restrict__ out)
{
    extern __shared__ char smem[];
    const uint32_t sb = smem_u32(smem);
    float* Ps   = (float*)(smem + A9_PS);
    float* m_s  = (float*)(smem + A9_MLA);
    float* l_s  = m_s + 16;
    float* al_s = l_s + 16;

    const int b = blockIdx.y, t = threadIdx.x;
    const int wid = t >> 5, lane = t & 31;
    const int g = lane >> 2, tig = lane & 3;

    // fragment lane offsets
    const int aiQ  = (((lane >> 3) & 1) * 8 + (lane & 7)) * LDK + (lane >> 4) * 8;
    const int biK2 = (lane & 7) * LDK + ((lane >> 3) & 1) * 8;   // ldsm.x2 (lanes 0-15)
    const int aiP  = (((lane >> 3) & 1) * 8 + (lane & 7)) * LDP + (lane >> 4) * 8;
    const int biV  = ((lane >> 4) * 8 + (lane & 7)) * LDV + ((lane >> 3) & 1) * 8;

    const __half* gQ  = g_q  + (size_t)b * SEQ * HD;
    const __half* gK  = g_k  + (size_t)b * SEQ * HD;
    const __half* gVt = g_vt + (size_t)b * HD * SEQ;

    const float RSC = 0.08838834764831845f;
    const int sr = t >> 4, sc0 = (t & 15) * 4;   // softmax: 16 thr/row, 4 cols
    const int kr = t >> 2, kq = t & 3;           // K cp.async
    const int vr = t >> 1, vhh = t & 1;          // V cp.async

    for (int subt = 0; subt < 2; ++subt) {
        const int jt = subt ? (127 - blockIdx.x) : blockIdx.x;
        const int q0 = jt * 16;
        const int iters = (jt >> 2) + 1;

        // Q tile: 16 rows x 128 halves
        {
            const int r = t >> 4, dq = (t & 15) * 8;
            *(uint4*)(smem + A9_Q + (r * LDK + dq) * 2) =
                *(const uint4*)(gQ + (size_t)(q0 + r) * HD + dq);
        }
        if (t < 16) { m_s[t] = -1e30f; l_s[t] = 0.f; }

        float o[2][4];
        #pragma unroll
        for (int nt = 0; nt < 2; ++nt)
            #pragma unroll
            for (int q = 0; q < 4; ++q) o[nt][q] = 0.f;

        #pragma unroll
        for (int pi = 0; pi < 2; ++pi) {
            if (pi < iters) {
                const int k0 = pi * KT;
                const uint32_t k_d = sb + A9_K + pi * KSTG + kr * (LDK * 2) + kq * 64;
                const uint32_t v_d = sb + A9_V + pi * VSTG + vr * (LDV * 2) + vhh * 64;
                const __half* ks = gK  + (size_t)(k0 + kr) * HD + kq * 32;
                const __half* vs = gVt + (size_t)vr * SEQ + k0 + vhh * 32;
                #pragma unroll
                for (int j = 0; j < 4; ++j) {
                    cpa16(k_d + j * 16, ks + j * 8);
                    cpa16(v_d + j * 16, vs + j * 8);
                }
            }
            CP_COMMIT();
        }

        for (int it = 0; it < iters; ++it) {
            const int k0 = it * KT;
            const int st = it & 1;
            const uint32_t sK = sb + A9_K + st * KSTG;
            const uint32_t sV = sb + A9_V + st * VSTG;

            CP_WAIT1();
            __syncthreads();

            // ---- QK^T: S(16x64); warp wid -> n8 span [8*wid, 8*wid+8)
            float s4[4];
            #pragma unroll
            for (int q = 0; q < 4; ++q) s4[q] = 0.f;
            #pragma unroll
            for (int ks = 0; ks < 8; ++ks) {
                const int k0s = ks * 16;
                uint32_t qa[4], kk[2];
                ldsm4(qa, sb + A9_Q + 2 * (k0s + aiQ));
                ldsm2(kk, sK + 2 * (wid * 8 * LDK + k0s + biK2));
                mma16816h(s4, qa, kk);
            }
            {
                const int col = wid * 8 + tig * 2;
                *(float2*)&Ps[g * SPS + col]       = make_float2(s4[0], s4[1]);
                *(float2*)&Ps[(g + 8) * SPS + col] = make_float2(s4[2], s4[3]);
            }
            __syncthreads();

            // ---- softmax (16 threads/row, 4 cols each); pack P fp16
            {
                const int gq = q0 + sr;
                float sv[4];
                float rm = -1e30f;
                #pragma unroll
                for (int j = 0; j < 4; ++j) {
                    float v = Ps[sr * SPS + sc0 + j] * RSC;
                    if (k0 + sc0 + j > gq) v = -1e10f;
                    sv[j] = v;
                    rm = fmaxf(rm, v);
                }
                #pragma unroll
                for (int off = 8; off >= 1; off >>= 1)
                    rm = fmaxf(rm, __shfl_xor_sync(0xffffffffu, rm, off));
                const float mo = m_s[sr];
                const float mn = fmaxf(mo, rm);
                float rs = 0.f;
                uint32_t pph[2];
                #pragma unroll
                for (int j = 0; j < 2; ++j) {
                    float p0 = __expf(sv[2 * j] - mn);
                    float p1 = __expf(sv[2 * j + 1] - mn);
                    rs += p0 + p1;
                    pph[j] = pk2h(__float2half(p0), __float2half(p1));
                }
                #pragma unroll
                for (int off = 8; off >= 1; off >>= 1)
                    rs += __shfl_xor_sync(0xffffffffu, rs, off);
                *(uint2*)(smem + A9_PB + (sr * LDP + sc0) * 2) =
                    make_uint2(pph[0], pph[1]);
                if ((t & 15) == 0) {
                    const float al = __expf(mo - mn);
                    m_s[sr]  = mn;
                    al_s[sr] = al;
                    l_s[sr]  = l_s[sr] * al + rs;
                }
            }
            __syncthreads();

            // ---- PV: O(16x128) = P(16x64) V; warp wid -> d span [16*wid,+16)
            {
                const float a0 = al_s[g];
                const float a1 = al_s[g + 8];
                #pragma unroll
                for (int nt = 0; nt < 2; ++nt) {
                    o[nt][0] *= a0; o[nt][1] *= a0;
                    o[nt][2] *= a1; o[nt][3] *= a1;
                }
                #pragma unroll
                for (int ks = 0; ks < 4; ++ks) {
                    const int k0s = ks * 16;
                    uint32_t pa[4], vb[4];
                    ldsm4(pa, sb + A9_PB + 2 * (k0s + aiP));
                    ldsm4(vb, sV + 2 * (wid * 16 * LDV + k0s + biV));
                    #pragma unroll
                    for (int nt = 0; nt < 2; ++nt)
                        mma16816h(o[nt], pa, &vb[nt * 2]);
                }
            }
            __syncthreads();

            if (it + 2 < iters) {
                const int kn = (it + 2) * KT;
                const uint32_t k_d = sb + A9_K + st * KSTG + kr * (LDK * 2) + kq * 64;
                const uint32_t v_d = sb + A9_V + st * VSTG + vr * (LDV * 2) + vhh * 64;
                const __half* ks = gK  + (size_t)(kn + kr) * HD + kq * 32;
                const __half* vs = gVt + (size_t)vr * SEQ + kn + vhh * 32;
                #pragma unroll
                for (int j = 0; j < 4; ++j) {
                    cpa16(k_d + j * 16, ks + j * 8);
                    cpa16(v_d + j * 16, vs + j * 8);
                }
            }
            CP_COMMIT();
        }

        // ---- epilogue
        {
            const float li0 = 1.f / l_s[g];
            const float li1 = 1.f / l_s[g + 8];
            float* op0 = out + ((size_t)b * SEQ + q0 + g) * HD + wid * 16;
            float* op1 = op0 + 8 * HD;
            #pragma unroll
            for (int nt = 0; nt < 2; ++nt) {
                const int d = nt * 8 + tig * 2;
                *(float2*)(op0 + d) = make_float2(o[nt][0] * li0, o[nt][1] * li0);
                *(float2*)(op1 + d) = make_float2(o[nt][2] * li1, o[nt][3] * li1);
            }
        }
        __syncthreads();   // before subt=1 reuses Q/stats/smem
    }
}

// ---------------------------------------------------------------------------
extern "C" void kernel_launch(void* const* d_in, const int* in_sizes, int n_in,
                              void* d_out, int out_size)
{
    const float* X  = (const float*)d_in[0];
    const float* Wq = (const float*)d_in[1];
    const float* bq = (const float*)d_in[2];
    const float* Wk = (const float*)d_in[3];
    const float* bk = (const float*)d_in[4];
    const float* Wv = (const float*)d_in[5];
    const float* bv = (const float*)d_in[6];
    float* out = (float*)d_out;

    prep_w<<<192, 256>>>(Wq, Wk, Wv);
    prep_x<<<512, 256>>>(X);

    cudaFuncSetAttribute(qkv6, cudaFuncAttributeMaxDynamicSharedMemorySize,
                         QSM6_TOTAL);
    qkv6<<<dim3(128, 3), 256, QSM6_TOTAL>>>(bq, bk, bv);

    cudaFuncSetAttribute(attn9, cudaFuncAttributeMaxDynamicSharedMemorySize,
                         ASM9_TOTAL);
    attn9<<<dim3(64, 4), 256, ASM9_TOTAL>>>(out);
}

// round 17
// speedup vs baseline: 1.1992x; 1.1992x over previous
#include <cuda_runtime.h>
#include <cuda_fp16.h>
#include <cstdint>

#define EMBED 2048
#define HD    128
#define NB    4
#define SEQ   2048

__device__ __align__(16) __half g_Wh[3 * HD * EMBED];
__device__ __align__(16) __half g_xh[(size_t)NB * SEQ * EMBED];
__device__ __align__(16) __half g_q [NB * SEQ * HD];
__device__ __align__(16) __half g_k [NB * SEQ * HD];
__device__ __align__(16) __half g_vt[NB * HD * SEQ];

__device__ __forceinline__ uint32_t pk2h(__half a, __half b) {
    return ((uint32_t)__half_as_ushort(b) << 16) | __half_as_ushort(a);
}
__device__ __forceinline__ uint32_t smem_u32(const void* p) {
    uint32_t a;
    asm("{ .reg .u64 t; cvta.to.shared.u64 t, %1; cvt.u32.u64 %0, t; }"
        : "=r"(a) : "l"(p));
    return a;
}
__device__ __forceinline__ void mma16816h(float* c, const uint32_t* a,
                                          const uint32_t* b) {
    asm volatile(
        "mma.sync.aligned.m16n8k16.row.col.f32.f16.f16.f32 "
        "{%0,%1,%2,%3}, {%4,%5,%6,%7}, {%8,%9}, {%0,%1,%2,%3};"
        : "+f"(c[0]), "+f"(c[1]), "+f"(c[2]), "+f"(c[3])
        : "r"(a[0]), "r"(a[1]), "r"(a[2]), "r"(a[3]), "r"(b[0]), "r"(b[1]));
}
__device__ __forceinline__ void ldsm4(uint32_t* r, uint32_t saddr) {
    asm volatile("ldmatrix.sync.aligned.m8n8.x4.shared.b16 {%0,%1,%2,%3}, [%4];"
                 : "=r"(r[0]), "=r"(r[1]), "=r"(r[2]), "=r"(r[3]) : "r"(saddr));
}
__device__ __forceinline__ void cpa16(uint32_t dst, const void* src) {
    asm volatile("cp.async.cg.shared.global [%0], [%1], 16;"
                 :: "r"(dst), "l"(__cvta_generic_to_global(src)) : "memory");
}
#define CP_COMMIT() asm volatile("cp.async.commit_group;" ::: "memory")
#define CP_WAIT1()  asm volatile("cp.async.wait_group 1;" ::: "memory")
#define CP_WAIT0()  asm volatile("cp.async.wait_group 0;" ::: "memory")

// ---------------------------------------------------------------------------
// prep_all: blocks 0..191 -> W fp32 -> rne fp16 [w][n][k];
//           blocks 192..703 -> X fp32 -> rne fp16.
// ---------------------------------------------------------------------------
__global__ __launch_bounds__(256)
void prep_all(const float* __restrict__ X,
              const float* __restrict__ Wq, const float* __restrict__ Wk,
              const float* __restrict__ Wv)
{
    const int t = threadIdx.x;
    if (blockIdx.x < 192) {
        __shared__ float Ws[32][132];
        const int w  = blockIdx.x >> 6;
        const int k0 = (blockIdx.x & 63) * 32;
        const float* __restrict__ W = (w == 0) ? Wq : (w == 1 ? Wk : Wv);

        #pragma unroll
        for (int l = 0; l < 16; ++l) {
            int idx = t + l * 256;
            int kk = idx >> 7, n = idx & 127;
            Ws[kk][n] = W[(size_t)(k0 + kk) * HD + n];
        }
        __syncthreads();

        const int n = t >> 1, kh = (t & 1) * 16;
        __half* dst = g_Wh + (size_t)w * HD * EMBED + (size_t)n * EMBED + k0 + kh;
        #pragma unroll
        for (int g = 0; g < 2; ++g) {
            uint32_t hp[4];
            #pragma unroll
            for (int e = 0; e < 4; ++e)
                hp[e] = pk2h(__float2half(Ws[kh + g * 8 + e * 2][n]),
                             __float2half(Ws[kh + g * 8 + e * 2 + 1][n]));
            *(uint4*)(dst + g * 8) = make_uint4(hp[0], hp[1], hp[2], hp[3]);
        }
    } else {
        const size_t N8 = (size_t)NB * SEQ * EMBED / 8;
        const size_t nthr = 512 * 256;
        for (size_t c = (size_t)(blockIdx.x - 192) * 256 + t; c < N8; c += nthr) {
            float4 v0 = *(const float4*)(X + c * 8);
            float4 v1 = *(const float4*)(X + c * 8 + 4);
            uint4 o;
            o.x = pk2h(__float2half(v0.x), __float2half(v0.y));
            o.y = pk2h(__float2half(v0.z), __float2half(v0.w));
            o.z = pk2h(__float2half(v1.x), __float2half(v1.y));
            o.w = pk2h(__float2half(v1.z), __float2half(v1.w));
            *(uint4*)(g_xh + c * 8) = o;
        }
    }
}

// ---------------------------------------------------------------------------
// qkv6 (R14-passing, unchanged): FP16 GEMM, KC=32, grid (128, 3), 3 CTAs/SM.
// ---------------------------------------------------------------------------
#define KC    32
#define LDB   40
#define A6STG (64 * LDB * 2)
#define B6STG (128 * LDB * 2)
#define O6_A  0
#define O6_B  (2 * A6STG)
#define O6_BIAS 34048
#define QSM6_TOTAL (O6_BIAS + 512)

__global__ __launch_bounds__(256, 3)
void qkv6(const float* __restrict__ bq, const float* __restrict__ bk,
          const float* __restrict__ bv)
{
    extern __shared__ char smem[];
    const uint32_t sb = smem_u32(smem);
    float* biasS = (float*)(smem + O6_BIAS);

    const int wsel = blockIdx.y;
    const int m0   = blockIdx.x * 64;
    const int t    = threadIdx.x;
    const int wid  = t >> 5, lane = t & 31;
    const int g    = lane >> 2, tig = lane & 3;
    const int wm   = wid >> 2, wn = wid & 3;

    const int aiA = (((lane >> 3) & 1) * 8 + (lane & 7)) * LDB + (lane >> 4) * 8;
    const int biB = ((lane >> 4) * 8 + (lane & 7)) * LDB + ((lane >> 3) & 1) * 8;

    if (t < 128) {
        const float* bias = (wsel == 0) ? bq : (wsel == 1 ? bk : bv);
        biasS[t] = bias[t];
    }

    const __half* Wh = g_Wh + (size_t)wsel * HD * EMBED;
    const int ar = t >> 2, aq = t & 3;
    const int br = t >> 1, bhh = t & 1;

    float c[2][4][4];
    #pragma unroll
    for (int i = 0; i < 2; ++i)
        #pragma unroll
        for (int j = 0; j < 4; ++j)
            #pragma unroll
            for (int q = 0; q < 4; ++q) c[i][j][q] = 0.f;

    #pragma unroll
    for (int pi = 0; pi < 2; ++pi) {
        const int kb = pi * KC;
        cpa16(sb + O6_A + pi * A6STG + ar * (LDB * 2) + aq * 16,
              g_xh + (size_t)(m0 + ar) * EMBED + kb + aq * 8);
        {
            const __half* src = Wh + (size_t)br * EMBED + kb + bhh * 16;
            const uint32_t dst = sb + O6_B + pi * B6STG + br * (LDB * 2) + bhh * 32;
            cpa16(dst, src);
            cpa16(dst + 16, src + 8);
        }
        CP_COMMIT();
    }

    for (int kt = 0; kt < EMBED / KC; ++kt) {
        const int st = kt & 1;
        const uint32_t sA = sb + O6_A + st * A6STG;
        const uint32_t sB = sb + O6_B + st * B6STG;

        CP_WAIT1();
        __syncthreads();

        #pragma unroll
        for (int ks = 0; ks < 2; ++ks) {
            const int ko = ks * 16;
            uint32_t a[2][4], bb[2][4];
            #pragma unroll
            for (int mi = 0; mi < 2; ++mi)
                ldsm4(a[mi], sA + 2 * ((wm * 32 + mi * 16) * LDB + ko + aiA));
            #pragma unroll
            for (int h = 0; h < 2; ++h)
                ldsm4(bb[h], sB + 2 * ((wn * 32 + h * 16) * LDB + ko + biB));
            #pragma unroll
            for (int mi = 0; mi < 2; ++mi)
                #pragma unroll
                for (int nt = 0; nt < 4; ++nt)
                    mma16816h(c[mi][nt], a[mi], &bb[nt >> 1][(nt & 1) * 2]);
        }
        __syncthreads();

        if (kt + 2 < EMBED / KC) {
            const int kb = (kt + 2) * KC;
            cpa16(sb + O6_A + st * A6STG + ar * (LDB * 2) + aq * 16,
                  g_xh + (size_t)(m0 + ar) * EMBED + kb + aq * 8);
            {
                const __half* src = Wh + (size_t)br * EMBED + kb + bhh * 16;
                const uint32_t dst = sb + O6_B + st * B6STG + br * (LDB * 2) + bhh * 32;
                cpa16(dst, src);
                cpa16(dst + 16, src + 8);
            }
        }
        CP_COMMIT();
    }

    __syncthreads();
    float (*Ct)[132] = (float (*)[132])smem;
    #pragma unroll
    for (int mi = 0; mi < 2; ++mi) {
        const int r = wm * 32 + mi * 16 + g;
        #pragma unroll
        for (int nt = 0; nt < 4; ++nt) {
            const int n = wn * 32 + nt * 8 + tig * 2;
            Ct[r][n]         = c[mi][nt][0] + biasS[n];
            Ct[r][n + 1]     = c[mi][nt][1] + biasS[n + 1];
            Ct[r + 8][n]     = c[mi][nt][2] + biasS[n];
            Ct[r + 8][n + 1] = c[mi][nt][3] + biasS[n + 1];
        }
    }
    __syncthreads();

    const int batch = m0 >> 11, s0 = m0 & 2047;
    if (wsel < 2) {
        const int r = t >> 2, dq = (t & 3) * 32;
        __half* dst = (wsel == 0 ? g_q : g_k)
            + ((size_t)batch * SEQ + s0 + r) * HD + dq;
        #pragma unroll
        for (int qq = 0; qq < 4; ++qq) {
            uint32_t hp[4];
            #pragma unroll
            for (int e = 0; e < 4; ++e)
                hp[e] = pk2h(__float2half(Ct[r][dq + qq * 8 + e * 2]),
                             __float2half(Ct[r][dq + qq * 8 + e * 2 + 1]));
            *(uint4*)(dst + qq * 8) = make_uint4(hp[0], hp[1], hp[2], hp[3]);
        }
    } else {
        const int d = t >> 1, sch = (t & 1) * 32;
        __half* dst = g_vt + ((size_t)batch * HD + d) * SEQ + s0 + sch;
        #pragma unroll
        for (int qq = 0; qq < 4; ++qq) {
            uint32_t hp[4];
            #pragma unroll
            for (int e = 0; e < 4; ++e)
                hp[e] = pk2h(__float2half(Ct[sch + qq * 8 + e * 2][d]),
                             __float2half(Ct[sch + qq * 8 + e * 2 + 1][d]));
            *(uint4*)(dst + qq * 8) = make_uint4(hp[0], hp[1], hp[2], hp[3]);
        }
    }
}

// ---------------------------------------------------------------------------
// attn10: software-pipelined flash attention.
// Phase A = PV(i) || QK(i+1)  (independent -> MMA pipe stays busy);
// Phase B = softmax(i+1) || prefetch issue.  2 barriers/iter.
// K 3-ring, V 2-ring -> one full iteration of cp.async slack.
// 32-row q-tiles, grid (32, 4), balanced pairing {x, 63-x}.
// ---------------------------------------------------------------------------
#define KT   64
#define LDK  136
#define LDV  72
#define LDP  72
#define SPS  68
#define KSTG (KT * LDK * 2)      // 17408
#define VSTG (HD * LDV * 2)      // 18432

#define AO_Q    0                            // 8704
#define AO_K    8704                         // 3 * 17408 -> 60928
#define AO_V    60928                        // 2 * 18432 -> 97792
#define AO_PS   97792                        // 8704 -> 106496
#define AO_PB   106496                       // 2 * 4608 -> 115712
#define AO_MLA  115712                       // 384
#define ASM_TOTAL 116096

__global__ __launch_bounds__(256)
void attn10(float* __restrict__ out)
{
    extern __shared__ char smem[];
    const uint32_t sb = smem_u32(smem);
    float* Ps   = (float*)(smem + AO_PS);
    float* m_s  = (float*)(smem + AO_MLA);
    float* l_s  = m_s + 32;
    float* al_s = l_s + 32;

    const int b = blockIdx.y, t = threadIdx.x;
    const int wid = t >> 5, lane = t & 31;
    const int g = lane >> 2, tig = lane & 3;
    const int wm = wid & 1, wn = wid >> 1;

    const int aiQ = (((lane >> 3) & 1) * 8 + (lane & 7)) * LDK + (lane >> 4) * 8;
    const int biK = ((lane >> 4) * 8 + (lane & 7)) * LDK + ((lane >> 3) & 1) * 8;
    const int aiP = (((lane >> 3) & 1) * 8 + (lane & 7)) * LDP + (lane >> 4) * 8;
    const int biV = ((lane >> 4) * 8 + (lane & 7)) * LDV + ((lane >> 3) & 1) * 8;

    const __half* gQ  = g_q  + (size_t)b * SEQ * HD;
    const __half* gK  = g_k  + (size_t)b * SEQ * HD;
    const __half* gVt = g_vt + (size_t)b * HD * SEQ;

    const float RSC = 0.08838834764831845f;
    const int sr = t >> 3, sc0 = (t & 7) * 8;
    const int kr = t >> 2, kq = t & 3;
    const int vr = t >> 1, vhh = t & 1;

    for (int subt = 0; subt < 2; ++subt) {
        const int jt = subt ? (63 - blockIdx.x) : blockIdx.x;
        const int q0 = jt * 32;
        const int iters = (jt >> 1) + 1;

        // Q tile
        {
            const int r = t >> 3, dq = (t & 7) * 16;
            const __half* sh = gQ + (size_t)(q0 + r) * HD + dq;
            *(uint4*)(smem + AO_Q + (r * LDK + dq) * 2)     = *(const uint4*)sh;
            *(uint4*)(smem + AO_Q + (r * LDK + dq + 8) * 2) = *(const uint4*)(sh + 8);
        }
        if (t < 32) { m_s[t] = -1e30f; l_s[t] = 0.f; }

        float o[4][4];
        #pragma unroll
        for (int nt = 0; nt < 4; ++nt)
            #pragma unroll
            for (int q = 0; q < 4; ++q) o[nt][q] = 0.f;

        // ---- prologue loads: G0={K0,V0} G1={K1,V1} G2={K2}
        #pragma unroll
        for (int pi = 0; pi < 3; ++pi) {
            if (pi < iters) {
                const int k0 = pi * KT;
                const uint32_t k_d = sb + AO_K + pi * KSTG + kr * (LDK * 2) + kq * 64;
                const __half* ks = gK + (size_t)(k0 + kr) * HD + kq * 32;
                #pragma unroll
                for (int j = 0; j < 4; ++j) cpa16(k_d + j * 16, ks + j * 8);
                if (pi < 2) {
                    const uint32_t v_d = sb + AO_V + pi * VSTG + vr * (LDV * 2) + vhh * 64;
                    const __half* vs = gVt + (size_t)vr * SEQ + k0 + vhh * 32;
                    #pragma unroll
                    for (int j = 0; j < 4; ++j) cpa16(v_d + j * 16, vs + j * 8);
                }
            }
            CP_COMMIT();
        }
        CP_WAIT0();
        __syncthreads();

        // ---- prologue compute: QK(0) -> Ps ; softmax(0) -> Pb[0]
        {
            float s4[2][4];
            #pragma unroll
            for (int nt = 0; nt < 2; ++nt)
                #pragma unroll
                for (int q = 0; q < 4; ++q) s4[nt][q] = 0.f;
            const uint32_t sK = sb + AO_K;
            #pragma unroll
            for (int ks = 0; ks < 8; ++ks) {
                const int k0s = ks * 16;
                uint32_t qa[4], kk[4];
                ldsm4(qa, sb + AO_Q + 2 * (wm * 16 * LDK + k0s + aiQ));
                ldsm4(kk, sK + 2 * (wn * 16 * LDK + k0s + biK));
                #pragma unroll
                for (int nt = 0; nt < 2; ++nt)
                    mma16816h(s4[nt], qa, &kk[nt * 2]);
            }
            const int row0 = wm * 16 + g;
            #pragma unroll
            for (int nt = 0; nt < 2; ++nt) {
                const int col = wn * 16 + nt * 8 + tig * 2;
                *(float2*)&Ps[row0 * SPS + col] = make_float2(s4[nt][0], s4[nt][1]);
                *(float2*)&Ps[(row0 + 8) * SPS + col] = make_float2(s4[nt][2], s4[nt][3]);
            }
        }
        __syncthreads();
        {
            const int gq = q0 + sr;
            float sv[8];
            float rm = -1e30f;
            #pragma unroll
            for (int j = 0; j < 8; ++j) {
                float v = Ps[sr * SPS + sc0 + j] * RSC;
                if (sc0 + j > gq) v = -1e10f;      // k0 = 0
                sv[j] = v;
                rm = fmaxf(rm, v);
            }
            #pragma unroll
            for (int off = 4; off >= 1; off >>= 1)
                rm = fmaxf(rm, __shfl_xor_sync(0xffffffffu, rm, off));
            const float mn = rm;                    // m old = -inf
            float rs = 0.f;
            uint32_t pph[4];
            #pragma unroll
            for (int j = 0; j < 4; ++j) {
                float p0 = __expf(sv[2 * j] - mn);
                float p1 = __expf(sv[2 * j + 1] - mn);
                rs += p0 + p1;
                pph[j] = pk2h(__float2half(p0), __float2half(p1));
            }
            #pragma unroll
            for (int off = 4; off >= 1; off >>= 1)
                rs += __shfl_xor_sync(0xffffffffu, rs, off);
            *(uint4*)(smem + AO_PB + (sr * LDP + sc0) * 2) =
                make_uint4(pph[0], pph[1], pph[2], pph[3]);
            if ((t & 7) == 0) {
                m_s[sr]  = mn;
                al_s[sr] = 1.f;
                l_s[sr]  = rs;
            }
        }
        __syncthreads();

        // ---- main pipelined loop
        for (int it = 0; it < iters; ++it) {
            // ===== phase A: PV(it) || QK(it+1)
            {
                const float a0 = al_s[wm * 16 + g];
                const float a1 = al_s[wm * 16 + g + 8];
                #pragma unroll
                for (int nt = 0; nt < 4; ++nt) {
                    o[nt][0] *= a0; o[nt][1] *= a0;
                    o[nt][2] *= a1; o[nt][3] *= a1;
                }
                const uint32_t sV  = sb + AO_V + (it & 1) * VSTG;
                const uint32_t sPb = sb + AO_PB + (it & 1) * 4608;
                #pragma unroll
                for (int ks = 0; ks < 4; ++ks) {
                    const int k0s = ks * 16;
                    uint32_t pa[4], vb[2][4];
                    ldsm4(pa, sPb + 2 * (wm * 16 * LDP + k0s + aiP));
                    #pragma unroll
                    for (int h = 0; h < 2; ++h)
                        ldsm4(vb[h], sV + 2 * ((wn * 32 + h * 16) * LDV + k0s + biV));
                    #pragma unroll
                    for (int nt = 0; nt < 4; ++nt)
                        mma16816h(o[nt], pa, &vb[nt >> 1][(nt & 1) * 2]);
                }
            }
            if (it + 1 < iters) {
                float s4[2][4];
                #pragma unroll
                for (int nt = 0; nt < 2; ++nt)
                    #pragma unroll
                    for (int q = 0; q < 4; ++q) s4[nt][q] = 0.f;
                const uint32_t sK = sb + AO_K + ((it + 1) % 3) * KSTG;
                #pragma unroll
                for (int ks = 0; ks < 8; ++ks) {
                    const int k0s = ks * 16;
                    uint32_t qa[4], kk[4];
                    ldsm4(qa, sb + AO_Q + 2 * (wm * 16 * LDK + k0s + aiQ));
                    ldsm4(kk, sK + 2 * (wn * 16 * LDK + k0s + biK));
                    #pragma unroll
                    for (int nt = 0; nt < 2; ++nt)
                        mma16816h(s4[nt], qa, &kk[nt * 2]);
                }
                const int row0 = wm * 16 + g;
                #pragma unroll
                for (int nt = 0; nt < 2; ++nt) {
                    const int col = wn * 16 + nt * 8 + tig * 2;
                    *(float2*)&Ps[row0 * SPS + col] = make_float2(s4[nt][0], s4[nt][1]);
                    *(float2*)&Ps[(row0 + 8) * SPS + col] = make_float2(s4[nt][2], s4[nt][3]);
                }
            }
            __syncthreads();

            // ===== phase B: softmax(it+1) || prefetch {K(it+3), V(it+2)}
            if (it + 1 < iters) {
                const int k0n = (it + 1) * KT;
                const int gq = q0 + sr;
                float sv[8];
                float rm = -1e30f;
                #pragma unroll
                for (int j = 0; j < 8; ++j) {
                    float v = Ps[sr * SPS + sc0 + j] * RSC;
                    if (k0n + sc0 + j > gq) v = -1e10f;
                    sv[j] = v;
                    rm = fmaxf(rm, v);
                }
                #pragma unroll
                for (int off = 4; off >= 1; off >>= 1)
                    rm = fmaxf(rm, __shfl_xor_sync(0xffffffffu, rm, off));
                const float mo = m_s[sr];
                const float mn = fmaxf(mo, rm);
                float rs = 0.f;
                uint32_t pph[4];
                #pragma unroll
                for (int j = 0; j < 4; ++j) {
                    float p0 = __expf(sv[2 * j] - mn);
                    float p1 = __expf(sv[2 * j + 1] - mn);
                    rs += p0 + p1;
                    pph[j] = pk2h(__float2half(p0), __float2half(p1));
                }
                #pragma unroll
                for (int off = 4; off >= 1; off >>= 1)
                    rs += __shfl_xor_sync(0xffffffffu, rs, off);
                *(uint4*)(smem + AO_PB + ((it + 1) & 1) * 4608 + (sr * LDP + sc0) * 2) =
                    make_uint4(pph[0], pph[1], pph[2], pph[3]);
                if ((t & 7) == 0) {
                    const float al = __expf(mo - mn);
                    m_s[sr]  = mn;
                    al_s[sr] = al;
                    l_s[sr]  = l_s[sr] * al + rs;
                }
            }
            // prefetch
            {
                if (it + 3 < iters) {
                    const int kn = (it + 3) * KT;
                    const uint32_t k_d = sb + AO_K + ((it + 3) % 3) * KSTG
                        + kr * (LDK * 2) + kq * 64;
                    const __half* ks = gK + (size_t)(kn + kr) * HD + kq * 32;
                    #pragma unroll
                    for (int j = 0; j < 4; ++j) cpa16(k_d + j * 16, ks + j * 8);
                }
                if (it + 2 < iters) {
                    const int kn = (it + 2) * KT;
                    const uint32_t v_d = sb + AO_V + (it & 1) * VSTG
                        + vr * (LDV * 2) + vhh * 64;
                    const __half* vs = gVt + (size_t)vr * SEQ + kn + vhh * 32;
                    #pragma unroll
                    for (int j = 0; j < 4; ++j) cpa16(v_d + j * 16, vs + j * 8);
                }
                CP_COMMIT();
            }
            if (it + 1 < iters) {
                CP_WAIT1();
                __syncthreads();
            }
        }

        // ---- epilogue
        {
            const float li0 = 1.f / l_s[wm * 16 + g];
            const float li1 = 1.f / l_s[wm * 16 + g + 8];
            float* op0 = out + ((size_t)b * SEQ + q0 + wm * 16 + g) * HD;
            float* op1 = op0 + 8 * HD;
            #pragma unroll
            for (int nt = 0; nt < 4; ++nt) {
                const int d = wn * 32 + nt * 8 + tig * 2;
                *(float2*)(op0 + d) = make_float2(o[nt][0] * li0, o[nt][1] * li0);
                *(float2*)(op1 + d) = make_float2(o[nt][2] * li1, o[nt][3] * li1);
            }
        }
        CP_WAIT0();          // drain pipeline before subt=1 reuses stages
        __syncthreads();
    }
}

// ---------------------------------------------------------------------------
extern "C" void kernel_launch(void* const* d_in, const int* in_sizes, int n_in,
                              void* d_out, int out_size)
{
    const float* X  = (const float*)d_in[0];
    const float* Wq = (const float*)d_in[1];
    const float* bq = (const float*)d_in[2];
    const float* Wk = (const float*)d_in[3];
    const float* bk = (const float*)d_in[4];
    const float* Wv = (const float*)d_in[5];
    const float* bv = (const float*)d_in[6];
    float* out = (float*)d_out;

    prep_all<<<704, 256>>>(X, Wq, Wk, Wv);

    cudaFuncSetAttribute(qkv6, cudaFuncAttributeMaxDynamicSharedMemorySize,
                         QSM6_TOTAL);
    qkv6<<<dim3(128, 3), 256, QSM6_TOTAL>>>(bq, bk, bv);

    cudaFuncSetAttribute(attn10, cudaFuncAttributeMaxDynamicSharedMemorySize,
                         ASM_TOTAL);
    attn10<<<dim3(32, 4), 256, ASM_TOTAL>>>(out);
}